// round 2
// baseline (speedup 1.0000x reference)
#include <cuda_runtime.h>
#include <cstdint>

#define BB   2
#define SS   2048
#define HH   16
#define DHH  64
#define DMM  1024

typedef unsigned long long ull;

// Scratch (allocation-free rule: __device__ globals)
__device__ float g_Q[(size_t)BB * HH * SS * DHH];
__device__ float g_K[(size_t)BB * HH * SS * DHH];
__device__ float g_V[(size_t)BB * HH * SS * DHH];
__device__ float g_ctx[(size_t)BB * SS * DMM];

// ---- packed f32x2 helpers (sm_103a FFMA2 path; ptxas never auto-emits) ----
__device__ __forceinline__ void ffma2(ull& d, ull a, ull b) {
    asm("fma.rn.f32x2 %0, %1, %2, %0;" : "+l"(d) : "l"(a), "l"(b));
}
__device__ __forceinline__ ull pack2(float x, float y) {
    ull r;
    asm("mov.b64 %0, {%1, %2};" : "=l"(r) : "f"(x), "f"(y));
    return r;
}
__device__ __forceinline__ ull mul2(ull a, ull b) {
    ull r;
    asm("mul.rn.f32x2 %0, %1, %2;" : "=l"(r) : "l"(a), "l"(b));
    return r;
}
__device__ __forceinline__ float2 unpack2(ull v) {
    float2 f;
    asm("mov.b64 {%0, %1}, %2;" : "=f"(f.x), "=f"(f.y) : "l"(v));
    return f;
}

// ---------------------------------------------------------------------------
// Tiled fp32 GEMM with FFMA2: C[M=4096, N=1024] = A @ W + bias
// 128x128 tile, 256 threads, 8x8 microtile (accumulated as 8x4 f32x2 pairs).
// ---------------------------------------------------------------------------
template <bool SCATTER>
__device__ __forceinline__ void gemm_body(const float* __restrict__ A,
                                          const float* __restrict__ W,
                                          const float* __restrict__ bias,
                                          float* __restrict__ out) {
    __shared__ float As[16 * 132];  // transposed: As[k][m], padded stride 132
    __shared__ float Bs[16 * 132];  // Bs[k][n]

    const int M0 = blockIdx.x * 128;
    const int N0 = blockIdx.y * 128;
    const int tid = threadIdx.x;
    const int ty = tid >> 4;   // rows  m = M0 + ty*8 ..
    const int tx = tid & 15;   // cols  n = N0 + tx*8 ..

    ull acc2[8][4];
#pragma unroll
    for (int i = 0; i < 8; i++)
#pragma unroll
        for (int j = 0; j < 4; j++) acc2[i][j] = 0ull;

    for (int kt = 0; kt < DMM; kt += 16) {
        // Load A tile 128x16, store transposed As[k][m]
#pragma unroll
        for (int i = 0; i < 2; i++) {
            int f = tid + i * 256;
            int row = f >> 2;
            int c4 = f & 3;
            float4 v = *(const float4*)&A[(size_t)(M0 + row) * DMM + kt + c4 * 4];
            As[(c4 * 4 + 0) * 132 + row] = v.x;
            As[(c4 * 4 + 1) * 132 + row] = v.y;
            As[(c4 * 4 + 2) * 132 + row] = v.z;
            As[(c4 * 4 + 3) * 132 + row] = v.w;
        }
        // Load W tile 16x128 row-major
#pragma unroll
        for (int i = 0; i < 2; i++) {
            int f = tid + i * 256;
            int kr = f >> 5;
            int c4 = f & 31;
            *(float4*)&Bs[kr * 132 + c4 * 4] =
                *(const float4*)&W[(size_t)(kt + kr) * DMM + N0 + c4 * 4];
        }
        __syncthreads();

#pragma unroll
        for (int kk = 0; kk < 16; kk++) {
            float a[8];
            *(float4*)&a[0] = *(const float4*)&As[kk * 132 + ty * 8];
            *(float4*)&a[4] = *(const float4*)&As[kk * 132 + ty * 8 + 4];
            ulonglong2 b01 = *(const ulonglong2*)&Bs[kk * 132 + tx * 8];
            ulonglong2 b23 = *(const ulonglong2*)&Bs[kk * 132 + tx * 8 + 4];
#pragma unroll
            for (int i = 0; i < 8; i++) {
                ull ad = pack2(a[i], a[i]);
                ffma2(acc2[i][0], ad, b01.x);
                ffma2(acc2[i][1], ad, b01.y);
                ffma2(acc2[i][2], ad, b23.x);
                ffma2(acc2[i][3], ad, b23.y);
            }
        }
        __syncthreads();
    }

#pragma unroll
    for (int i = 0; i < 8; i++) {
        int mm = M0 + ty * 8 + i;
#pragma unroll
        for (int jp = 0; jp < 4; jp++) {
            float2 v2 = unpack2(acc2[i][jp]);
            float vv[2] = {v2.x, v2.y};
#pragma unroll
            for (int u = 0; u < 2; u++) {
                int n = N0 + tx * 8 + jp * 2 + u;
                float v = vv[u] + bias[n];
                if (SCATTER) {
                    int bidx = mm >> 11;
                    int srow = mm & (SS - 1);
                    int hh = n >> 6;
                    int dd = n & 63;
                    out[((size_t)(bidx * HH + hh) * SS + srow) * DHH + dd] = v;
                } else {
                    out[(size_t)mm * DMM + n] = v;
                }
            }
        }
    }
}

__global__ void __launch_bounds__(256)
qkv_kernel(const float* __restrict__ x,
           const float* __restrict__ Wq, const float* __restrict__ bq,
           const float* __restrict__ Wk, const float* __restrict__ bk,
           const float* __restrict__ Wv, const float* __restrict__ bv) {
    int z = blockIdx.z;
    const float* W = (z == 0) ? Wq : (z == 1) ? Wk : Wv;
    const float* bias = (z == 0) ? bq : (z == 1) ? bk : bv;
    float* out = (z == 0) ? g_Q : (z == 1) ? g_K : g_V;
    gemm_body<true>(x, W, bias, out);
}

__global__ void __launch_bounds__(256)
oproj_kernel(const float* __restrict__ Wo, const float* __restrict__ bo,
             float* __restrict__ out) {
    gemm_body<false>(g_ctx, Wo, bo, out);
}

// ---------------------------------------------------------------------------
// Flash-style causal attention with additive pos_bias, FFMA2 inner loops.
// One CTA per (b, h, 64-row q tile). 256 threads = 16(ty rows) x 16(tx cols),
// 4x4 microtile.
// ---------------------------------------------------------------------------
#define AST 68  // padded smem row stride (floats), keeps float4/16B alignment

__global__ void __launch_bounds__(256)
attn_kernel(const float* __restrict__ pb_all) {
    extern __shared__ float sm[];
    float* Qs = sm;                 // [d][r]  (64 x AST)
    float* Ks = Qs + 64 * AST;      // [d][j]
    float* Vs = Ks + 64 * AST;      // [j][d]
    float* Ps = Vs + 64 * AST;      // [j][r]

    const int qt = (int)gridDim.x - 1 - (int)blockIdx.x;  // longest first
    const int h = blockIdx.y;
    const int bb = blockIdx.z;
    const int q0 = qt * 64;

    const size_t hoff = (size_t)(bb * HH + h) * SS * DHH;
    const float* Qg = g_Q + hoff;
    const float* Kg = g_K + hoff;
    const float* Vg = g_V + hoff;
    const float* pb = pb_all + (size_t)h * SS * SS;

    const int tid = threadIdx.x;
    const int ty = tid >> 4;   // query rows r = ty*4 .. +3
    const int tx = tid & 15;   // key cols  j = tx*4 .. +3

    for (int idx = tid; idx < 64 * DHH; idx += 256) {
        int r = idx >> 6, d = idx & 63;
        Qs[d * AST + r] = Qg[(size_t)(q0 + r) * DHH + d];
    }

    float m[4], l[4];
    ull o2[4][2];
#pragma unroll
    for (int i = 0; i < 4; i++) {
        m[i] = -3.0e38f;
        l[i] = 0.f;
        o2[i][0] = 0ull;
        o2[i][1] = 0ull;
    }

    for (int kt = 0; kt <= qt; kt++) {
        const int k0 = kt * 64;
        __syncthreads();  // previous PV done (and Q load visible on iter 0)
        for (int idx = tid; idx < 64 * DHH; idx += 256) {
            int r = idx >> 6, d = idx & 63;
            Ks[d * AST + r] = Kg[(size_t)(k0 + r) * DHH + d];
            Vs[r * AST + d] = Vg[(size_t)(k0 + r) * DHH + d];
        }
        __syncthreads();

        // stage pos_bias (coalesced float4 per row)
        float4 brow[4];
#pragma unroll
        for (int i = 0; i < 4; i++)
            brow[i] = *(const float4*)&pb[(size_t)(q0 + ty * 4 + i) * SS + k0 + tx * 4];

        // scores: 4x4 dot over d=64 via FFMA2 (pairs along j)
        ull s2[4][2];
#pragma unroll
        for (int i = 0; i < 4; i++) { s2[i][0] = 0ull; s2[i][1] = 0ull; }

#pragma unroll
        for (int d = 0; d < 64; d++) {
            float4 qv = *(const float4*)&Qs[d * AST + ty * 4];
            ulonglong2 kv = *(const ulonglong2*)&Ks[d * AST + tx * 4];
            float qa[4] = {qv.x, qv.y, qv.z, qv.w};
#pragma unroll
            for (int i = 0; i < 4; i++) {
                ull qd = pack2(qa[i], qa[i]);
                ffma2(s2[i][0], qd, kv.x);
                ffma2(s2[i][1], qd, kv.y);
            }
        }

        // unpack, scale + bias
        float s[4][4];
#pragma unroll
        for (int i = 0; i < 4; i++) {
            float2 p0 = unpack2(s2[i][0]);
            float2 p1 = unpack2(s2[i][1]);
            s[i][0] = p0.x * 0.125f + brow[i].x;
            s[i][1] = p0.y * 0.125f + brow[i].y;
            s[i][2] = p1.x * 0.125f + brow[i].z;
            s[i][3] = p1.y * 0.125f + brow[i].w;
        }
        // causal mask — only diagonal tile can violate
        if (kt == qt) {
#pragma unroll
            for (int i = 0; i < 4; i++)
#pragma unroll
                for (int j = 0; j < 4; j++)
                    if (tx * 4 + j > ty * 4 + i) s[i][j] = -1.0e9f;
        }

        // online softmax per row (16 tx lanes of same ty reduce via shfl_xor)
#pragma unroll
        for (int i = 0; i < 4; i++) {
            float tmax = fmaxf(fmaxf(s[i][0], s[i][1]), fmaxf(s[i][2], s[i][3]));
#pragma unroll
            for (int off = 8; off >= 1; off >>= 1)
                tmax = fmaxf(tmax, __shfl_xor_sync(0xffffffffu, tmax, off));
            float mn = fmaxf(m[i], tmax);
            float corr = __expf(m[i] - mn);
            m[i] = mn;
            l[i] *= corr;
            ull c2 = pack2(corr, corr);
            o2[i][0] = mul2(o2[i][0], c2);
            o2[i][1] = mul2(o2[i][1], c2);
            float psum = 0.f;
#pragma unroll
            for (int j = 0; j < 4; j++) {
                float p = __expf(s[i][j] - mn);
                s[i][j] = p;
                psum += p;
            }
#pragma unroll
            for (int off = 8; off >= 1; off >>= 1)
                psum += __shfl_xor_sync(0xffffffffu, psum, off);
            l[i] += psum;
        }

        // write P transposed for the PV pass
#pragma unroll
        for (int i = 0; i < 4; i++)
#pragma unroll
            for (int j = 0; j < 4; j++)
                Ps[(tx * 4 + j) * AST + ty * 4 + i] = s[i][j];
        __syncthreads();

        // O += P @ V via FFMA2 (pairs along dim c)
#pragma unroll 8
        for (int j = 0; j < 64; j++) {
            float4 p4 = *(const float4*)&Ps[j * AST + ty * 4];
            ulonglong2 v2 = *(const ulonglong2*)&Vs[j * AST + tx * 4];
            float pa[4] = {p4.x, p4.y, p4.z, p4.w};
#pragma unroll
            for (int i = 0; i < 4; i++) {
                ull pd = pack2(pa[i], pa[i]);
                ffma2(o2[i][0], pd, v2.x);
                ffma2(o2[i][1], pd, v2.y);
            }
        }
    }

    // epilogue: normalized context in [B, S, D_MODEL] layout (merge heads)
    float* ctx = g_ctx + (size_t)bb * SS * DMM;
#pragma unroll
    for (int i = 0; i < 4; i++) {
        float inv = 1.f / l[i];
        float2 a0 = unpack2(o2[i][0]);
        float2 a1 = unpack2(o2[i][1]);
        float ov[4] = {a0.x, a0.y, a1.x, a1.y};
#pragma unroll
        for (int c = 0; c < 4; c++)
            ctx[(size_t)(q0 + ty * 4 + i) * DMM + h * DHH + tx * 4 + c] = ov[c] * inv;
    }
}

// ---------------------------------------------------------------------------
// Launch
// ---------------------------------------------------------------------------
extern "C" void kernel_launch(void* const* d_in, const int* in_sizes, int n_in,
                              void* d_out, int out_size) {
    const float* x  = (const float*)d_in[0];
    // d_in[1] = mask: deterministic causal tril -> applied analytically
    const float* Wq = (const float*)d_in[2];
    const float* bq = (const float*)d_in[3];
    const float* Wk = (const float*)d_in[4];
    const float* bk = (const float*)d_in[5];
    const float* Wv = (const float*)d_in[6];
    const float* bv = (const float*)d_in[7];
    const float* Wo = (const float*)d_in[8];
    const float* bo = (const float*)d_in[9];
    const float* pb = (const float*)d_in[10];

    const int smem_attn = 4 * 64 * AST * sizeof(float);  // 69632 B
    cudaFuncSetAttribute(attn_kernel, cudaFuncAttributeMaxDynamicSharedMemorySize,
                         smem_attn);

    qkv_kernel<<<dim3(32, 8, 3), 256>>>(x, Wq, bq, Wk, bk, Wv, bv);
    attn_kernel<<<dim3(32, 16, 2), 256, smem_attn>>>(pb);
    oproj_kernel<<<dim3(32, 8, 1), 256>>>(Wo, bo, (float*)d_out);
}